// round 2
// baseline (speedup 1.0000x reference)
#include <cuda_runtime.h>

#define FULLMASK 0xFFFFFFFFu
#define SCALING  2.0f   // alpha / r = 32 / 16

// scratch (allocation-free rule: __device__ globals)
__device__ float g_v[16384 * 32];   // per token: [ s*g1*ce[0:16] | s*g2*ce[0:16] ]
__device__ int   g_eidx[16384];     // e1 | (e2 << 8)

// ---------------------------------------------------------------------------
// packed f32x2 helpers (Blackwell): 2 independent fp32 lanes per instruction
// ---------------------------------------------------------------------------
static __device__ __forceinline__ unsigned long long ffma2(unsigned long long a,
                                                           unsigned long long b,
                                                           unsigned long long c) {
    unsigned long long d;
    asm("fma.rn.f32x2 %0, %1, %2, %3;" : "=l"(d) : "l"(a), "l"(b), "l"(c));
    return d;
}
static __device__ __forceinline__ unsigned long long addx2(unsigned long long a,
                                                           unsigned long long b) {
    unsigned long long d;
    asm("add.rn.f32x2 %0, %1, %2;" : "=l"(d) : "l"(a), "l"(b));
    return d;
}

union F4  { float4 f; unsigned long long u[2]; };
union U2F { unsigned long long u; float2 f; };

// ---------------------------------------------------------------------------
// Routing epilogue: red[0..7] = logits, red[8..23] = ce. All lanes hold all
// 24 reduced values (post-butterfly). Compile-time indexing only (no spills).
// ---------------------------------------------------------------------------
static __device__ __forceinline__ void route_one(const float* red, int t, int lane) {
    int e1 = 0; float v1 = red[0];
#pragma unroll
    for (int e = 1; e < 8; e++) if (red[e] > v1) { v1 = red[e]; e1 = e; }
    int e2 = 0; float v2 = -3.0e38f;
#pragma unroll
    for (int e = 0; e < 8; e++) if (e != e1 && red[e] > v2) { v2 = red[e]; e2 = e; }
    // softmax over {v1, v2}, v1 >= v2 (matches jax: subtract-max form)
    float ex  = __expf(v2 - v1);
    float inv = 1.0f / (1.0f + ex);
    float sg1 = SCALING * inv;
    float sg2 = SCALING * ex * inv;
    float* vo = g_v + (size_t)t * 32;
    // one predicated coalesced 128B store per warp; indices compile-time
#pragma unroll
    for (int r = 0; r < 16; r++) {
        if (lane == r)      vo[r]      = sg1 * red[8 + r];
        if (lane == r + 16) vo[r + 16] = sg2 * red[8 + r];
    }
    if (lane == 0) g_eidx[t] = e1 | (e2 << 8);
}

// ---------------------------------------------------------------------------
// Kernel 1: logits + ce + routing. 256 threads, 96KB smem (24x1024 weights).
// Each warp: 2 tokens per pass, full k in registers, weights broadcast-free
// lane-strided from smem (conflict-free LDS128).
// ---------------------------------------------------------------------------
__global__ void __launch_bounds__(256)
k_route(const float4* __restrict__ X4,   // x, row = 256 float4
        const float4* __restrict__ WR4,  // w_route: 2048 float4
        const float4* __restrict__ CP4,  // compress: 4096 float4
        int npairs)
{
    extern __shared__ float4 sW4[];      // 6144 float4 = 96KB; rows 0..7 route, 8..23 compress
    for (int i = threadIdx.x; i < 2048; i += 256) sW4[i]        = WR4[i];
    for (int i = threadIdx.x; i < 4096; i += 256) sW4[2048 + i] = CP4[i];
    __syncthreads();

    const int lane = threadIdx.x & 31;
    const int gw   = blockIdx.x * 8 + (threadIdx.x >> 5);
    const int nw   = gridDim.x * 8;

    for (int p = gw; p < npairs; p += nw) {
        const int t0 = 2 * p;

        F4 x0[8], x1[8];
#pragma unroll
        for (int j = 0; j < 8; j++) {
            x0[j].f = X4[(size_t)t0 * 256 + j * 32 + lane];
            x1[j].f = X4[(size_t)(t0 + 1) * 256 + j * 32 + lane];
        }

        unsigned long long a0[24], a1[24];
#pragma unroll
        for (int o = 0; o < 24; o++) { a0[o] = 0ull; a1[o] = 0ull; }

#pragma unroll
        for (int j = 0; j < 8; j++) {
#pragma unroll
            for (int o = 0; o < 24; o++) {
                F4 w; w.f = sW4[o * 256 + j * 32 + lane];
                a0[o] = ffma2(w.u[0], x0[j].u[0], a0[o]);
                a0[o] = ffma2(w.u[1], x0[j].u[1], a0[o]);
                a1[o] = ffma2(w.u[0], x1[j].u[0], a1[o]);
                a1[o] = ffma2(w.u[1], x1[j].u[1], a1[o]);
            }
        }

        // horizontal (k-parity) add, then 5-stage butterfly over lanes
        float r0[24], r1[24];
#pragma unroll
        for (int o = 0; o < 24; o++) {
            U2F u;
            u.u = a0[o]; r0[o] = u.f.x + u.f.y;
            u.u = a1[o]; r1[o] = u.f.x + u.f.y;
        }
#pragma unroll
        for (int off = 16; off >= 1; off >>= 1) {
#pragma unroll
            for (int o = 0; o < 24; o++) {
                r0[o] += __shfl_xor_sync(FULLMASK, r0[o], off);
                r1[o] += __shfl_xor_sync(FULLMASK, r1[o], off);
            }
        }

        route_one(r0, t0,     lane);
        route_one(r1, t0 + 1, lane);
    }
}

// ---------------------------------------------------------------------------
// Kernel 2: expert-major combine. CTA = 64 tokens x 256 outputs, 256 threads
// (1 output column each). Per expert: routed[e][o][0:16] cached in registers,
// stream that expert's token list, accumulate into an exclusive smem column.
// Deterministic (serial list build), no atomics in the hot path.
// ---------------------------------------------------------------------------
#define K2_SMEM_BYTES (64*256*4 + 64*32*4 + 8*64*4 + 64*4 + 8*4)

__global__ void __launch_bounds__(256)
k_combine(const float4* __restrict__ R4all,  // routed: [8][1024][16] -> e*4096 + o*4 in f4
          float4* __restrict__ out4)         // out, row = 256 float4
{
    extern __shared__ float smem2[];
    float* sacc  = smem2;                    // [64][256]
    float* sv    = smem2 + 64 * 256;         // [64][32]
    int*   slist = (int*)(sv + 64 * 32);     // [8][64]
    int*   se    = slist + 8 * 64;           // [64]
    int*   scnt  = se + 64;                  // [8]

    const int tid = threadIdx.x;
    const int ob  = blockIdx.x;              // 0..3 (output block)
    const int t0  = blockIdx.y * 64;         // token base

    if (tid < 64) se[tid] = g_eidx[t0 + tid];
    {
        const float4* v4g = (const float4*)(g_v + (size_t)t0 * 32);
        float4* sv4 = (float4*)sv;
        for (int i = tid; i < 512; i += 256) sv4[i] = v4g[i];
    }
    __syncthreads();

    if (tid == 0) {
        int c[8] = {0, 0, 0, 0, 0, 0, 0, 0};
        for (int t = 0; t < 64; t++) {
            int ee = se[t];
            int e1 = ee & 255, e2 = (ee >> 8) & 255;
            slist[e1 * 64 + c[e1]] = t;       c[e1]++;
            slist[e2 * 64 + c[e2]] = t | 64;  c[e2]++;   // bit6 = second-expert half
        }
#pragma unroll
        for (int e = 0; e < 8; e++) scnt[e] = c[e];
    } else {
        float4 z = make_float4(0.f, 0.f, 0.f, 0.f);
        float4* sa4 = (float4*)sacc;
        for (int i = tid - 1; i < 4096; i += 255) sa4[i] = z;
    }
    __syncthreads();

    const int o = ob * 256 + tid;            // global output column owned by this thread
    for (int e = 0; e < 8; e++) {
        const int n = scnt[e];
        if (n == 0) continue;
        F4 rr0, rr1, rr2, rr3;
        const float4* R4 = R4all + (size_t)e * 4096 + (size_t)o * 4;
        rr0.f = R4[0]; rr1.f = R4[1]; rr2.f = R4[2]; rr3.f = R4[3];
        const int* lst = slist + e * 64;
        for (int k = 0; k < n; k++) {
            int ent = lst[k];                           // smem broadcast
            int tl  = ent & 63;
            const F4* v4 = (const F4*)(sv + tl * 32 + ((ent & 64) >> 2));
            F4 v0 = v4[0], vA = v4[1], vB = v4[2], vC = v4[3];  // broadcast LDS128
            unsigned long long b0 = 0ull, b1 = 0ull, b2 = 0ull, b3 = 0ull;
            b0 = ffma2(rr0.u[0], v0.u[0], b0); b0 = ffma2(rr0.u[1], v0.u[1], b0);
            b1 = ffma2(rr1.u[0], vA.u[0], b1); b1 = ffma2(rr1.u[1], vA.u[1], b1);
            b2 = ffma2(rr2.u[0], vB.u[0], b2); b2 = ffma2(rr2.u[1], vB.u[1], b2);
            b3 = ffma2(rr3.u[0], vC.u[0], b3);
            b3 = ffma2(rr3.u[1], vC.u[1], b3);
            b0 = addx2(b0, b1); b2 = addx2(b2, b3); b0 = addx2(b0, b2);
            U2F u; u.u = b0;
            sacc[tl * 256 + tid] += u.f.x + u.f.y;      // exclusive column, no race
        }
    }
    __syncthreads();

    const float4* sa4 = (const float4*)sacc;
    for (int i = tid; i < 4096; i += 256) {
        int tl = i >> 6, c4 = i & 63;
        out4[(size_t)(t0 + tl) * 256 + ob * 64 + c4] = sa4[i];
    }
}

// ---------------------------------------------------------------------------
// Launch. Inputs identified by element count (all distinct):
//   x = 16777216, w_route = 8192, compress = 16384, routed = 131072
// ---------------------------------------------------------------------------
extern "C" void kernel_launch(void* const* d_in, const int* in_sizes, int n_in,
                              void* d_out, int out_size) {
    const float *x = nullptr, *wr = nullptr, *cp = nullptr, *rt = nullptr;
    long long n_x = 0;
    for (int i = 0; i < n_in; i++) {
        int s = in_sizes[i];
        if      (s == 8192)   wr = (const float*)d_in[i];
        else if (s == 16384)  cp = (const float*)d_in[i];
        else if (s == 131072) rt = (const float*)d_in[i];
        else { x = (const float*)d_in[i]; n_x = s; }
    }
    const int n_tok = (int)(n_x / 1024);   // 16384

    cudaFuncSetAttribute(k_route,   cudaFuncAttributeMaxDynamicSharedMemorySize, 96 * 1024);
    cudaFuncSetAttribute(k_combine, cudaFuncAttributeMaxDynamicSharedMemorySize, K2_SMEM_BYTES);

    k_route<<<256, 256, 96 * 1024>>>((const float4*)x, (const float4*)wr,
                                     (const float4*)cp, n_tok / 2);

    dim3 g2(4, n_tok / 64);
    k_combine<<<g2, 256, K2_SMEM_BYTES>>>((const float4*)rt, (float4*)d_out);
}

// round 3
// speedup vs baseline: 2.5158x; 2.5158x over previous
#include <cuda_runtime.h>

#define SCALING 2.0f     // alpha / r = 32 / 16
#define TOK     16384

// scratch (allocation-free rule: __device__ globals)
__device__ float g_v[TOK * 32];   // per token: [ s*g1*ce[0:16] | s*g2*ce[0:16] ]
__device__ int   g_eidx[TOK];     // e1 | (e2 << 8)

static __device__ __forceinline__ unsigned long long ffma2(unsigned long long a,
                                                           unsigned long long b,
                                                           unsigned long long c) {
    unsigned long long d;
    asm("fma.rn.f32x2 %0, %1, %2, %3;" : "=l"(d) : "l"(a), "l"(b), "l"(c));
    return d;
}

union F4  { float4 f; unsigned long long u[2]; };
union U2F { unsigned long long u; float2 f; };

// ---------------------------------------------------------------------------
// Kernel 1: logits(8) + ce(16) + routing.
// CTA = 256 thr = 8 warps; warp = k-slice (128 k), lane = token (32 tokens).
// Persistent grid over 512 token-groups. No shuffles; per-lane-complete
// accumulators. Weights broadcast from smem; x double-buffered, xor-swizzled.
// ---------------------------------------------------------------------------
#define K1_W_F4   6144                 // 24 rows * 256 float4
#define K1_X_F4   2048                 // 32 tok * 64 f4 (one chunk buffer)
#define K1_SMEM   ((K1_W_F4 + 2*K1_X_F4) * 16 + 24*8*32*4)   // 188416 B

__global__ void __launch_bounds__(256, 1)
k_route(const float4* __restrict__ X4,   // x: row = 256 float4
        const float4* __restrict__ WR4,  // w_route: 2048 float4
        const float4* __restrict__ CP4,  // compress: 4096 float4
        int ngroups)
{
    extern __shared__ float4 sm4[];
    float4* sW   = sm4;                          // [24][256] f4
    float4* sX   = sm4 + K1_W_F4;                // 2 x [32][64] f4 (swizzled)
    float*  sred = (float*)(sm4 + K1_W_F4 + 2 * K1_X_F4);  // [24][8][32]

    const int tid  = threadIdx.x;
    const int lane = tid & 31;       // = token within group
    const int ks   = tid >> 5;       // k-slice (warp id)
    const int stok = (tid >> 6);     // staging: tok = p*4 + stok
    const int sf4  = tid & 63;       // staging: f4 column

    for (int i = tid; i < 2048; i += 256) sW[i]        = WR4[i];
    for (int i = tid; i < 4096; i += 256) sW[2048 + i] = CP4[i];

    for (int g = blockIdx.x; g < ngroups; g += gridDim.x) {
        const int tb = g * 32;
        float4 st[8];

        // prologue: chunk 0 -> buf0
        {
            const float4* xb = X4 + (size_t)tb * 256;
#pragma unroll
            for (int p = 0; p < 8; p++)
                st[p] = xb[(size_t)(p * 4 + stok) * 256 + sf4];
        }
#pragma unroll
        for (int p = 0; p < 8; p++) {
            int tok  = p * 4 + stok;
            int phys = (sf4 & 32) | ((sf4 ^ tok) & 31);
            sX[tok * 64 + phys] = st[p];
        }
        __syncthreads();   // S1: buf0 + (first group) sW visible

        unsigned long long acc[24];
#pragma unroll
        for (int o = 0; o < 24; o++) acc[o] = 0ull;

        for (int c = 0; c < 4; c++) {
            if (c < 3) {
                const float4* xb = X4 + (size_t)tb * 256 + (c + 1) * 64;
#pragma unroll
                for (int p = 0; p < 8; p++)
                    st[p] = xb[(size_t)(p * 4 + stok) * 256 + sf4];
            }
            const float4* xbuf  = sX + (c & 1) * K1_X_F4;
            const float4* wbase = sW + c * 64 + ks * 8;
#pragma unroll
            for (int b = 0; b < 8; b++) {
                int f4   = ks * 8 + b;
                int phys = (f4 & 32) | ((f4 ^ lane) & 31);
                F4 xv; xv.f = xbuf[lane * 64 + phys];
#pragma unroll
                for (int o = 0; o < 24; o++) {
                    F4 wv; wv.f = wbase[o * 256 + b];
                    acc[o] = ffma2(wv.u[0], xv.u[0], acc[o]);
                    acc[o] = ffma2(wv.u[1], xv.u[1], acc[o]);
                }
            }
            if (c < 3) {
#pragma unroll
                for (int p = 0; p < 8; p++) {
                    int tok  = p * 4 + stok;
                    int phys = (sf4 & 32) | ((sf4 ^ tok) & 31);
                    sX[((c + 1) & 1) * K1_X_F4 + tok * 64 + phys] = st[p];
                }
                __syncthreads();
            }
        }

        // cross-warp k-reduction
#pragma unroll
        for (int o = 0; o < 24; o++) {
            U2F u; u.u = acc[o];
            sred[o * 256 + ks * 32 + lane] = u.f.x + u.f.y;
        }
        __syncthreads();   // S2

        if (ks == 0) {     // warp 0: lane = token; finish reduce + route
            float red[24];
#pragma unroll
            for (int o = 0; o < 24; o++) {
                float s = 0.f;
#pragma unroll
                for (int k8 = 0; k8 < 8; k8++) s += sred[o * 256 + k8 * 32 + lane];
                red[o] = s;
            }
            int e1 = 0; float v1 = red[0];
#pragma unroll
            for (int e = 1; e < 8; e++) if (red[e] > v1) { v1 = red[e]; e1 = e; }
            int e2 = 0; float v2 = -3.0e38f;
#pragma unroll
            for (int e = 0; e < 8; e++) if (e != e1 && red[e] > v2) { v2 = red[e]; e2 = e; }
            float ex  = __expf(v2 - v1);
            float inv = 1.0f / (1.0f + ex);
            float sg1 = SCALING * inv;
            float sg2 = SCALING * ex * inv;
            int t = tb + lane;
            float4* vo = (float4*)(g_v + (size_t)t * 32);
#pragma unroll
            for (int j = 0; j < 4; j++)
                vo[j] = make_float4(sg1 * red[8 + j*4], sg1 * red[9 + j*4],
                                    sg1 * red[10 + j*4], sg1 * red[11 + j*4]);
#pragma unroll
            for (int j = 0; j < 4; j++)
                vo[4 + j] = make_float4(sg2 * red[8 + j*4], sg2 * red[9 + j*4],
                                        sg2 * red[10 + j*4], sg2 * red[11 + j*4]);
            g_eidx[t] = e1 | (e2 << 8);
        }
        // next group's prologue STS targets sX (gated by S2); sred reused only
        // after next group's S2.
    }
}

// ---------------------------------------------------------------------------
// Kernel 2: expert-major combine. CTA = 64 tokens x 256 cols, 128 threads
// (2 cols each). Expert weights in regs, per-entry 8-deep FFMA2 chain per
// column, smem RMW into exclusive column (independent chains across entries).
// ---------------------------------------------------------------------------
#define K2_SMEM (64*256*4 + 64*32*4 + 8*64*4 + 64*4 + 8*4)   // 76064 B

__global__ void __launch_bounds__(128)
k_combine(const float4* __restrict__ R4,   // routed: [8][1024][16] -> e*4096 + o*4
          float4* __restrict__ out4)       // out: row = 256 float4
{
    extern __shared__ float sm[];
    float* sacc  = sm;                     // [64][256]
    float* sv    = sm + 64 * 256;          // [64][32]
    int*   slist = (int*)(sv + 64 * 32);   // [8][64]
    int*   se    = slist + 8 * 64;         // [64]
    int*   scnt  = se + 64;                // [8]

    const int tid = threadIdx.x;
    const int cb  = blockIdx.x;            // 0..3
    const int t0  = blockIdx.y * 64;

    if (tid < 64) se[tid] = g_eidx[t0 + tid];
    {
        const float4* vg = (const float4*)(g_v + (size_t)t0 * 32);
        float4* sv4 = (float4*)sv;
        for (int i = tid; i < 512; i += 128) sv4[i] = vg[i];
    }
    __syncthreads();

    if (tid == 0) {                        // deterministic serial list build
        int c[8] = {0,0,0,0,0,0,0,0};
        for (int t = 0; t < 64; t++) {
            int ee = se[t];
            int e1 = ee & 255, e2 = (ee >> 8) & 255;
            slist[e1 * 64 + c[e1]++] = t;
            slist[e2 * 64 + c[e2]++] = t | 64;   // bit6 = second-expert half
        }
#pragma unroll
        for (int e = 0; e < 8; e++) scnt[e] = c[e];
    } else {                               // others zero the accumulator tile
        float4 z = make_float4(0.f, 0.f, 0.f, 0.f);
        float4* sa4 = (float4*)sacc;
        for (int i = tid - 1; i < 4096; i += 127) sa4[i] = z;
    }
    __syncthreads();

    const int o0 = cb * 256 + tid;         // this thread's cols: o0, o0+128
    for (int e = 0; e < 8; e++) {
        const int n = scnt[e];
        if (!n) continue;
        F4 a0, a1, a2, a3, b0, b1, b2, b3;
        const float4* W  = R4 + (size_t)e * 4096 + (size_t)o0 * 4;
        a0.f = W[0];   a1.f = W[1];   a2.f = W[2];   a3.f = W[3];
        b0.f = W[512]; b1.f = W[513]; b2.f = W[514]; b3.f = W[515];  // o0+128
        const int* lst = slist + e * 64;
        int ent = lst[0];
        for (int k = 0; k < n; k++) {
            int entn = lst[(k + 1 < n) ? (k + 1) : k];   // prefetch
            int tl   = ent & 63;
            const F4* v = (const F4*)(sv + tl * 32 + ((ent & 64) >> 2));
            F4 v0 = v[0], v1 = v[1], v2 = v[2], v3 = v[3];   // broadcast
            unsigned long long x = 0ull, y = 0ull;
            x = ffma2(a0.u[0], v0.u[0], x); x = ffma2(a0.u[1], v0.u[1], x);
            x = ffma2(a1.u[0], v1.u[0], x); x = ffma2(a1.u[1], v1.u[1], x);
            x = ffma2(a2.u[0], v2.u[0], x); x = ffma2(a2.u[1], v2.u[1], x);
            x = ffma2(a3.u[0], v3.u[0], x); x = ffma2(a3.u[1], v3.u[1], x);
            y = ffma2(b0.u[0], v0.u[0], y); y = ffma2(b0.u[1], v0.u[1], y);
            y = ffma2(b1.u[0], v1.u[0], y); y = ffma2(b1.u[1], v1.u[1], y);
            y = ffma2(b2.u[0], v2.u[0], y); y = ffma2(b2.u[1], v2.u[1], y);
            y = ffma2(b3.u[0], v3.u[0], y); y = ffma2(b3.u[1], v3.u[1], y);
            U2F ux, uy; ux.u = x; uy.u = y;
            float* s0 = sacc + tl * 256 + tid;
            s0[0]   += ux.f.x + ux.f.y;    // exclusive columns, no race
            s0[128] += uy.f.x + uy.f.y;
            ent = entn;
        }
    }
    __syncthreads();

    const float4* sa4 = (const float4*)sacc;
    for (int i = tid; i < 4096; i += 128) {
        int tl = i >> 6, c4 = i & 63;
        out4[(size_t)(t0 + tl) * 256 + cb * 64 + c4] = sa4[i];
    }
}

// ---------------------------------------------------------------------------
// Launch. Inputs identified by element count (all distinct):
//   x = 16777216, w_route = 8192, compress = 16384, routed = 131072
// ---------------------------------------------------------------------------
extern "C" void kernel_launch(void* const* d_in, const int* in_sizes, int n_in,
                              void* d_out, int out_size) {
    const float *x = nullptr, *wr = nullptr, *cp = nullptr, *rt = nullptr;
    long long n_x = 0;
    for (int i = 0; i < n_in; i++) {
        int s = in_sizes[i];
        if      (s == 8192)   wr = (const float*)d_in[i];
        else if (s == 16384)  cp = (const float*)d_in[i];
        else if (s == 131072) rt = (const float*)d_in[i];
        else { x = (const float*)d_in[i]; n_x = s; }
    }
    const int n_tok = (int)(n_x / 1024);   // 16384

    cudaFuncSetAttribute(k_route,   cudaFuncAttributeMaxDynamicSharedMemorySize, K1_SMEM);
    cudaFuncSetAttribute(k_combine, cudaFuncAttributeMaxDynamicSharedMemorySize, K2_SMEM);

    k_route<<<148, 256, K1_SMEM>>>((const float4*)x, (const float4*)wr,
                                   (const float4*)cp, n_tok / 32);

    dim3 g2(4, n_tok / 64);
    k_combine<<<g2, 128, K2_SMEM>>>((const float4*)rt, (float4*)d_out);
}